// round 7
// baseline (speedup 1.0000x reference)
#include <cuda_runtime.h>
#include <cuda_bf16.h>
#include <math.h>
#include <stdint.h>

#define MT 4096      // B*T
#define CC 1024      // C
#define NH 16
#define HD 64
#define NC 16        // WKV chunks
#define CL 64        // chunk length (NC*CL = 1024 = T)

// ---------------- scratch (static device arrays; no allocations) ----------------
__device__ float g_sx  [MT*CC];   // sx; later reused as S0 (chunk initial states)
__device__ float g_xmix[MT*CC];   // xmix; later reused as S (chunk local end states)
__device__ float g_P   [MT*160];
__device__ float g_wx  [MT*CC];
__device__ float g_kx  [MT*CC];
__device__ float g_vx  [MT*CC];
__device__ float g_rx  [MT*CC];
__device__ float g_gx  [MT*CC];
__device__ float g_rr  [MT*CC];
__device__ float g_kk  [MT*CC];
__device__ float g_vv  [MT*CC];
__device__ float g_gg  [MT*CC];
__device__ float g_t1  [MT*64];   // t1; later reused as prodW
__device__ float g_wd  [MT*CC];
__device__ float g_og  [MT*CC];

__device__ __forceinline__ float* dbuf(int id) {
    switch (id) {
        case 0:  return g_sx;
        case 1:  return g_xmix;
        case 2:  return g_P;
        case 3:  return g_wx;
        case 4:  return g_kx;
        case 5:  return g_vx;
        case 6:  return g_rx;
        case 7:  return g_gx;
        case 8:  return g_rr;
        case 9:  return g_kk;
        case 10: return g_vv;
        case 11: return g_gg;
        case 12: return g_t1;
        case 13: return g_wd;
        default: return g_og;  // 14
    }
}

// ---------------- prep: sx = x_{t-1} - x_t ; xmix = x + sx*x_maa ----------------
__global__ void prep_kernel(const float* __restrict__ x, const float* __restrict__ x_maa) {
    int idx = (blockIdx.x * 256 + threadIdx.x) * 4;
    if (idx >= MT * CC) return;
    int row = idx / CC;
    int col = idx % CC;
    int t = row & 1023;
    float4 xc = *(const float4*)(x + idx);
    float4 xp;
    if (t == 0) xp = make_float4(0.f, 0.f, 0.f, 0.f);
    else        xp = *(const float4*)(x + idx - CC);
    float4 ma = *(const float4*)(x_maa + col);
    float4 s, m;
    s.x = xp.x - xc.x; s.y = xp.y - xc.y; s.z = xp.z - xc.z; s.w = xp.w - xc.w;
    m.x = fmaf(s.x, ma.x, xc.x); m.y = fmaf(s.y, ma.y, xc.y);
    m.z = fmaf(s.z, ma.z, xc.z); m.w = fmaf(s.w, ma.w, xc.w);
    *(float4*)(g_sx + idx)   = s;
    *(float4*)(g_xmix + idx) = m;
}

// ================= tf32 tensor-core GEMM primitives =================
__device__ __forceinline__ uint32_t f2tf32(float f) {
    uint32_t u;
    asm("cvt.rna.tf32.f32 %0, %1;" : "=r"(u) : "f"(f));
    return u;
}

__device__ __forceinline__ void mma_tf32(float* c, const uint32_t* a, const uint32_t* b) {
    asm volatile(
        "mma.sync.aligned.m16n8k8.row.col.f32.tf32.tf32.f32 "
        "{%0,%1,%2,%3}, {%4,%5,%6,%7}, {%8,%9}, {%0,%1,%2,%3};\n"
        : "+f"(c[0]), "+f"(c[1]), "+f"(c[2]), "+f"(c[3])
        : "r"(a[0]), "r"(a[1]), "r"(a[2]), "r"(a[3]), "r"(b[0]), "r"(b[1]));
}

__device__ __forceinline__ void cpa16(uint32_t dst, const void* src) {
    asm volatile("cp.async.cg.shared.global [%0], [%1], 16;" :: "r"(dst), "l"(src));
}

// ======= FAST path: M=4096, N=K=1024 fixed; 128x128 CTA tile, 4 warps, 64x64 warp tile,
//         cp.async double-buffered, raw fp32 in smem, cvt on fragment load.
//         RUNTIME epi (0=none, 2=silu) -> single instantiation, single smem block. =======
__device__ __forceinline__ void tf32_fast_body(
    const float* __restrict__ A, const float* __restrict__ B, float* __restrict__ C,
    int epi)
{
    __shared__ float As[2][128][20];   // 128 rows x 16 k (pad 20)
    __shared__ float Bs[2][16][132];   // 16 k x 128 n (pad 132)
    const int tid = threadIdx.x;
    const int lane = tid & 31, wid = tid >> 5;
    const int warp_m = (wid & 1) * 64, warp_n = (wid >> 1) * 64;
    const int grp = lane >> 2, qid = lane & 3;
    const int bm = blockIdx.y * 128, bn = blockIdx.x * 128;

    const uint32_t as_base = (uint32_t)__cvta_generic_to_shared(&As[0][0][0]);
    const uint32_t bs_base = (uint32_t)__cvta_generic_to_shared(&Bs[0][0][0]);

    const float* Arow = A + (size_t)(bm + tid) * 1024;           // thread -> A row
    const int br0 = tid >> 5, bcc = (tid & 31) * 4;              // B chunk mapping

    float acc[32][4];
#pragma unroll
    for (int i = 0; i < 32; ++i)
#pragma unroll
        for (int q = 0; q < 4; ++q) acc[i][q] = 0.f;

    auto issue = [&](int stage, int k0) {
        uint32_t ad = as_base + (uint32_t)stage * (128 * 20 * 4) + (uint32_t)tid * 80;
        const float* asrc = Arow + k0;
        cpa16(ad,      asrc);
        cpa16(ad + 16, asrc + 4);
        cpa16(ad + 32, asrc + 8);
        cpa16(ad + 48, asrc + 12);
        uint32_t bd = bs_base + (uint32_t)stage * (16 * 132 * 4);
#pragma unroll
        for (int q = 0; q < 4; ++q) {
            int r = br0 + q * 4;
            cpa16(bd + (uint32_t)(r * 132 + bcc) * 4,
                  B + (size_t)(k0 + r) * 1024 + bn + bcc);
        }
        asm volatile("cp.async.commit_group;");
    };

    issue(0, 0);

    const int nk = 64;   // K/16
    for (int kt = 0; kt < nk; ++kt) {
        int cur = kt & 1;
        if (kt + 1 < nk) {
            issue(cur ^ 1, (kt + 1) * 16);
            asm volatile("cp.async.wait_group 1;");
        } else {
            asm volatile("cp.async.wait_group 0;");
        }
        __syncthreads();

#pragma unroll
        for (int kk = 0; kk < 16; kk += 8) {
            uint32_t af[4][4], bf[8][2];
#pragma unroll
            for (int mt = 0; mt < 4; ++mt) {
                int r0 = warp_m + mt * 16 + grp;
                af[mt][0] = f2tf32(As[cur][r0][kk + qid]);
                af[mt][1] = f2tf32(As[cur][r0 + 8][kk + qid]);
                af[mt][2] = f2tf32(As[cur][r0][kk + qid + 4]);
                af[mt][3] = f2tf32(As[cur][r0 + 8][kk + qid + 4]);
            }
#pragma unroll
            for (int nt = 0; nt < 8; ++nt) {
                int c0 = warp_n + nt * 8 + grp;
                bf[nt][0] = f2tf32(Bs[cur][kk + qid][c0]);
                bf[nt][1] = f2tf32(Bs[cur][kk + qid + 4][c0]);
            }
#pragma unroll
            for (int mt = 0; mt < 4; ++mt)
#pragma unroll
                for (int nt = 0; nt < 8; ++nt)
                    mma_tf32(acc[mt * 8 + nt], af[mt], bf[nt]);
        }
        __syncthreads();
    }

    // epilogue (runtime epi; uniform branch)
    bool do_silu = (epi == 2);
#pragma unroll
    for (int mt = 0; mt < 4; ++mt) {
#pragma unroll
        for (int nt = 0; nt < 8; ++nt) {
            float* a = acc[mt * 8 + nt];
            int gr = bm + warp_m + mt * 16 + grp;
            int gc = bn + warp_n + nt * 8 + qid * 2;
            float v[4] = { a[0], a[1], a[2], a[3] };
            if (do_silu) {
#pragma unroll
                for (int q = 0; q < 4; ++q) {
                    float sg = 1.f / (1.f + expf(-v[q]));
                    v[q] = v[q] * sg;
                }
            }
            *(float2*)(C + (size_t)gr * 1024 + gc)       = make_float2(v[0], v[1]);
            *(float2*)(C + (size_t)(gr + 8) * 1024 + gc) = make_float2(v[2], v[3]);
        }
    }
}

// 4-way batched projections r/k/v/g (silu on g)
__global__ void __launch_bounds__(128)
tf32_proj4_fast(const float* __restrict__ Wr, const float* __restrict__ Wk,
                const float* __restrict__ Wv, const float* __restrict__ Wg) {
    int z = blockIdx.z;
    const float* A = (z == 0) ? g_rx : (z == 1) ? g_kx : (z == 2) ? g_vx : g_gx;
    const float* B = (z == 0) ? Wr : (z == 1) ? Wk : (z == 2) ? Wv : Wg;
    float* C       = (z == 0) ? g_rr : (z == 1) ? g_kk : (z == 2) ? g_vv : g_gg;
    tf32_fast_body(A, B, C, (z == 3) ? 2 : 0);
}

// single fast GEMM: C = og @ Wo  (final output)
__global__ void __launch_bounds__(128)
tf32_wo_fast(const float* __restrict__ Wo, float* __restrict__ out) {
    tf32_fast_body(g_og, Wo, out, 0);
}

// ======= guarded tf32 GEMM (small N), register-staged (R4 path, proven) =======
template<bool GUARD>
__device__ __forceinline__ void tf32_body(
    const float* __restrict__ A, const float* __restrict__ B, float* __restrict__ C,
    int N, int K, int epi)
{
    __shared__ float As[2][128][20];
    __shared__ float Bs[2][16][136];
    int tid = threadIdx.x;
    int bm = blockIdx.y * 128, bn = blockIdx.x * 128;
    int lane = tid & 31, wid = tid >> 5;
    int warp_m = (wid & 1) * 64, warp_n = (wid >> 1) * 32;
    int grp = lane >> 2, qid = lane & 3;

    int ar = tid >> 2, ac = (tid & 3) * 4;
    int br = tid >> 5, bc = (tid & 31) * 4;
    const float* Ap = A + (size_t)(bm + ar) * K + ac;
    const float* Bp = B + (size_t)br * N + bn + bc;
    bool bin = !GUARD || (bn + bc < N);

    float4 av0, av1, bv0, bv1;
    av0 = *(const float4*)Ap;
    av1 = *(const float4*)(Ap + (size_t)64 * K);
    if (bin) { bv0 = *(const float4*)Bp; bv1 = *(const float4*)(Bp + (size_t)8 * N); }
    else     { bv0 = make_float4(0,0,0,0); bv1 = bv0; }

    {
        As[0][ar][ac+0] = __uint_as_float(f2tf32(av0.x));
        As[0][ar][ac+1] = __uint_as_float(f2tf32(av0.y));
        As[0][ar][ac+2] = __uint_as_float(f2tf32(av0.z));
        As[0][ar][ac+3] = __uint_as_float(f2tf32(av0.w));
        As[0][ar+64][ac+0] = __uint_as_float(f2tf32(av1.x));
        As[0][ar+64][ac+1] = __uint_as_float(f2tf32(av1.y));
        As[0][ar+64][ac+2] = __uint_as_float(f2tf32(av1.z));
        As[0][ar+64][ac+3] = __uint_as_float(f2tf32(av1.w));
        float4 t0, t1;
        t0.x = __uint_as_float(f2tf32(bv0.x)); t0.y = __uint_as_float(f2tf32(bv0.y));
        t0.z = __uint_as_float(f2tf32(bv0.z)); t0.w = __uint_as_float(f2tf32(bv0.w));
        t1.x = __uint_as_float(f2tf32(bv1.x)); t1.y = __uint_as_float(f2tf32(bv1.y));
        t1.z = __uint_as_float(f2tf32(bv1.z)); t1.w = __uint_as_float(f2tf32(bv1.w));
        *(float4*)&Bs[0][br][bc]   = t0;
        *(float4*)&Bs[0][br+8][bc] = t1;
    }
    __syncthreads();

    float acc[16][4];
#pragma unroll
    for (int i = 0; i < 16; ++i)
#pragma unroll
        for (int q = 0; q < 4; ++q) acc[i][q] = 0.f;

    int nk = K >> 4;
    for (int kt = 0; kt < nk; ++kt) {
        int cur = kt & 1;
        bool more = (kt + 1 < nk);
        if (more) {
            const float* Ap2 = Ap + (kt + 1) * 16;
            const float* Bp2 = Bp + (size_t)(kt + 1) * 16 * N;
            av0 = *(const float4*)Ap2;
            av1 = *(const float4*)(Ap2 + (size_t)64 * K);
            if (bin) { bv0 = *(const float4*)Bp2; bv1 = *(const float4*)(Bp2 + (size_t)8 * N); }
        }
#pragma unroll
        for (int kk = 0; kk < 16; kk += 8) {
            uint32_t af[4][4], bf[4][2];
#pragma unroll
            for (int mt = 0; mt < 4; ++mt) {
                int r0 = warp_m + mt * 16 + grp;
                af[mt][0] = __float_as_uint(As[cur][r0][kk + qid]);
                af[mt][1] = __float_as_uint(As[cur][r0 + 8][kk + qid]);
                af[mt][2] = __float_as_uint(As[cur][r0][kk + qid + 4]);
                af[mt][3] = __float_as_uint(As[cur][r0 + 8][kk + qid + 4]);
            }
#pragma unroll
            for (int nt = 0; nt < 4; ++nt) {
                int c0 = warp_n + nt * 8 + grp;
                bf[nt][0] = __float_as_uint(Bs[cur][kk + qid][c0]);
                bf[nt][1] = __float_as_uint(Bs[cur][kk + qid + 4][c0]);
            }
#pragma unroll
            for (int mt = 0; mt < 4; ++mt)
#pragma unroll
                for (int nt = 0; nt < 4; ++nt)
                    mma_tf32(acc[mt * 4 + nt], af[mt], bf[nt]);
        }
        if (more) {
            int nxt = cur ^ 1;
            As[nxt][ar][ac+0] = __uint_as_float(f2tf32(av0.x));
            As[nxt][ar][ac+1] = __uint_as_float(f2tf32(av0.y));
            As[nxt][ar][ac+2] = __uint_as_float(f2tf32(av0.z));
            As[nxt][ar][ac+3] = __uint_as_float(f2tf32(av0.w));
            As[nxt][ar+64][ac+0] = __uint_as_float(f2tf32(av1.x));
            As[nxt][ar+64][ac+1] = __uint_as_float(f2tf32(av1.y));
            As[nxt][ar+64][ac+2] = __uint_as_float(f2tf32(av1.z));
            As[nxt][ar+64][ac+3] = __uint_as_float(f2tf32(av1.w));
            float4 t0, t1;
            if (!bin) { bv0 = make_float4(0,0,0,0); bv1 = bv0; }
            t0.x = __uint_as_float(f2tf32(bv0.x)); t0.y = __uint_as_float(f2tf32(bv0.y));
            t0.z = __uint_as_float(f2tf32(bv0.z)); t0.w = __uint_as_float(f2tf32(bv0.w));
            t1.x = __uint_as_float(f2tf32(bv1.x)); t1.y = __uint_as_float(f2tf32(bv1.y));
            t1.z = __uint_as_float(f2tf32(bv1.z)); t1.w = __uint_as_float(f2tf32(bv1.w));
            *(float4*)&Bs[nxt][br][bc]   = t0;
            *(float4*)&Bs[nxt][br+8][bc] = t1;
            __syncthreads();
        }
    }

#pragma unroll
    for (int mt = 0; mt < 4; ++mt) {
#pragma unroll
        for (int nt = 0; nt < 4; ++nt) {
            const float* a = acc[mt * 4 + nt];
            int gr = bm + warp_m + mt * 16 + grp;
            int gc = bn + warp_n + nt * 8 + qid * 2;
            if (GUARD && gc >= N) continue;
            float v[4] = { a[0], a[1], a[2], a[3] };
            if (epi == 1) {
#pragma unroll
                for (int q = 0; q < 4; ++q) v[q] = tanhf(v[q]);
            }
            *(float2*)(C + (size_t)gr * N + gc)       = make_float2(v[0], v[1]);
            *(float2*)(C + (size_t)(gr + 8) * N + gc) = make_float2(v[2], v[3]);
        }
    }
}

template<bool GUARD>
__global__ void __launch_bounds__(256)
tf32_gemm(int a_id, const float* __restrict__ Bw, float* __restrict__ Cext, int c_id,
          int N, int K, int epi) {
    const float* A = dbuf(a_id);
    float* C = (c_id < 0) ? Cext : dbuf(c_id);
    tf32_body<GUARD>(A, Bw, C, N, K, epi);
}

// ---------------- fp32 128x128x8 SGEMM (decay path only), EPI exp(-exp(.)) ----------------
__global__ void __launch_bounds__(256)
sgemm128_wd(const float* __restrict__ B, const float* __restrict__ extra) {
    const float* A = g_t1;    // [4096, 64]
    float* C = g_wd;
    const int N = CC, K = 64;
    __shared__ float As[2][8][128];
    __shared__ float Bs[2][8][128];
    int tid = threadIdx.x;
    int bm = blockIdx.y * 128, bn = blockIdx.x * 128;
    int arow = tid >> 1,  acol = (tid & 1) * 4;
    int brow = tid >> 5,  bcol = (tid & 31) * 4;
    const float* Ap = A + (size_t)(bm + arow) * K + acol;
    const float* Bp = B + (size_t)brow * N + bn + bcol;
    int tx = (tid & 15) * 8, ty = (tid >> 4) * 8;
    float acc[8][8] = {};

    float4 a4 = *(const float4*)Ap;
    float4 b4 = *(const float4*)Bp;
    As[0][acol + 0][arow] = a4.x; As[0][acol + 1][arow] = a4.y;
    As[0][acol + 2][arow] = a4.z; As[0][acol + 3][arow] = a4.w;
    *(float4*)&Bs[0][brow][bcol] = b4;
    __syncthreads();

    const int nk = K >> 3;
    for (int kt = 0; kt < nk; ++kt) {
        int cur = kt & 1;
        bool more = (kt + 1 < nk);
        float4 a4n, b4n;
        if (more) {
            a4n = *(const float4*)(Ap + (size_t)(kt + 1) * 8);
            b4n = *(const float4*)(Bp + (size_t)(kt + 1) * 8 * N);
        }
#pragma unroll
        for (int kk = 0; kk < 8; ++kk) {
            float ra[8], rb[8];
#pragma unroll
            for (int i = 0; i < 8; ++i) { ra[i] = As[cur][kk][ty + i]; rb[i] = Bs[cur][kk][tx + i]; }
#pragma unroll
            for (int i = 0; i < 8; ++i)
#pragma unroll
                for (int j = 0; j < 8; ++j)
                    acc[i][j] = fmaf(ra[i], rb[j], acc[i][j]);
        }
        if (more) {
            int nxt = cur ^ 1;
            As[nxt][acol + 0][arow] = a4n.x; As[nxt][acol + 1][arow] = a4n.y;
            As[nxt][acol + 2][arow] = a4n.z; As[nxt][acol + 3][arow] = a4n.w;
            *(float4*)&Bs[nxt][brow][bcol] = b4n;
            __syncthreads();
        }
    }

#pragma unroll
    for (int i = 0; i < 8; ++i) {
        size_t rowoff = (size_t)(bm + ty + i) * N;
#pragma unroll
        for (int j = 0; j < 8; j += 4) {
            float4 v;
            v.x = expf(-expf(extra[bn + tx + j + 0] + acc[i][j]));
            v.y = expf(-expf(extra[bn + tx + j + 1] + acc[i][j + 1]));
            v.z = expf(-expf(extra[bn + tx + j + 2] + acc[i][j + 2]));
            v.w = expf(-expf(extra[bn + tx + j + 3] + acc[i][j + 3]));
            *(float4*)(C + rowoff + bn + tx + j) = v;
        }
    }
}

// ---------------- fused K=32 mix GEMM + apply ----------------
__global__ void __launch_bounds__(256)
mix_kernel(const float* __restrict__ x,
           const float* __restrict__ w_maa, const float* __restrict__ k_maa,
           const float* __restrict__ v_maa, const float* __restrict__ r_maa,
           const float* __restrict__ gm_maa,
           const float* __restrict__ tm_w2) {
    int f = blockIdx.z;
    int bm = blockIdx.y * 128, bn = blockIdx.x * 128;
    __shared__ float Ps[128][33];
    __shared__ float Ws[32][128];
    int tid = threadIdx.x;
    for (int i = tid; i < 128 * 8; i += 256) {
        int r = i >> 3, c4 = (i & 7) * 4;
        float4 p4 = *(const float4*)(g_P + (size_t)(bm + r) * 160 + f * 32 + c4);
        Ps[r][c4] = p4.x; Ps[r][c4 + 1] = p4.y; Ps[r][c4 + 2] = p4.z; Ps[r][c4 + 3] = p4.w;
    }
    for (int i = tid; i < 32 * 32; i += 256) {
        int r = i >> 5, c4 = (i & 31) * 4;
        *(float4*)&Ws[r][c4] = *(const float4*)(tm_w2 + ((size_t)f * 32 + r) * 1024 + bn + c4);
    }
    __syncthreads();
    int tx = (tid & 15) * 8, ty = (tid >> 4) * 8;
    float acc[8][8] = {};
#pragma unroll
    for (int kk = 0; kk < 32; ++kk) {
        float ra[8], rb[8];
#pragma unroll
        for (int i = 0; i < 8; ++i) { ra[i] = Ps[ty + i][kk]; rb[i] = Ws[kk][tx + i]; }
#pragma unroll
        for (int i = 0; i < 8; ++i)
#pragma unroll
            for (int j = 0; j < 8; ++j)
                acc[i][j] = fmaf(ra[i], rb[j], acc[i][j]);
    }
    const float* maa = (f == 0) ? w_maa : (f == 1) ? k_maa : (f == 2) ? v_maa : (f == 3) ? r_maa : gm_maa;
    float* out = (f == 0) ? g_wx : (f == 1) ? g_kx : (f == 2) ? g_vx : (f == 3) ? g_rx : g_gx;
#pragma unroll
    for (int i = 0; i < 8; ++i) {
        size_t rowoff = (size_t)(bm + ty + i) * 1024;
#pragma unroll
        for (int j = 0; j < 8; ++j) {
            int gc = bn + tx + j;
            float m = acc[i][j];
            out[rowoff + gc] = fmaf(g_sx[rowoff + gc], maa[gc] + m, x[rowoff + gc]);
        }
    }
}

// ================= WKV: chunked parallel scan =================
__global__ void __launch_bounds__(256)
wkv_passA() {
    int wid  = blockIdx.x * 8 + (threadIdx.x >> 5);
    int lane = threadIdx.x & 31;
    int half = wid & 1, c = (wid >> 1) & (NC - 1), bh = wid >> 5;
    int b = bh >> 4, h = bh & 15;
    int j = half * 32 + lane;
    size_t base = (size_t)b * 1048576 + h * 64;
    float s[64];
#pragma unroll
    for (int i = 0; i < 64; ++i) s[i] = 0.f;
    float pw0 = 1.f, pw1 = 1.f;
    int t0 = c * CL;
    for (int t = 0; t < CL; ++t) {
        size_t off = base + (size_t)(t0 + t) * 1024;
        float k0 = g_kk[off + lane], k1 = g_kk[off + lane + 32];
        float w0 = g_wd[off + lane], w1 = g_wd[off + lane + 32];
        float vj = g_vv[off + j];
        pw0 *= w0; pw1 *= w1;
#pragma unroll
        for (int i = 0; i < 32; ++i) {
            float ki = __shfl_sync(0xffffffffu, k0, i);
            float wi = __shfl_sync(0xffffffffu, w0, i);
            s[i] = fmaf(wi, s[i], ki * vj);
        }
#pragma unroll
        for (int i = 0; i < 32; ++i) {
            float ki = __shfl_sync(0xffffffffu, k1, i);
            float wi = __shfl_sync(0xffffffffu, w1, i);
            s[32 + i] = fmaf(wi, s[32 + i], ki * vj);
        }
    }
    size_t sb = (size_t)bh * 65536 + (size_t)c * 4096;
#pragma unroll
    for (int i = 0; i < 64; ++i) g_xmix[sb + i * 64 + j] = s[i];
    g_t1[bh * 1024 + c * 64 + lane]      = pw0;
    g_t1[bh * 1024 + c * 64 + lane + 32] = pw1;
}

__global__ void wkv_combine() {
    int tid = blockIdx.x * 256 + threadIdx.x;       // 262144 = 64*64*64
    int bh = tid >> 12;
    int i  = (tid >> 6) & 63;
    int j  = tid & 63;
    size_t sb = (size_t)bh * 65536 + i * 64 + j;
    float s0 = 0.f;
#pragma unroll
    for (int c = 0; c < NC; ++c) {
        g_sx[sb + (size_t)c * 4096] = s0;
        float pw = g_t1[bh * 1024 + c * 64 + i];
        s0 = fmaf(pw, s0, g_xmix[sb + (size_t)c * 4096]);
    }
}

__global__ void __launch_bounds__(256)
wkv_passB(const float* __restrict__ u) {
    int wid  = blockIdx.x * 8 + (threadIdx.x >> 5);
    int lane = threadIdx.x & 31;
    int half = wid & 1, c = (wid >> 1) & (NC - 1), bh = wid >> 5;
    int b = bh >> 4, h = bh & 15;
    int j = half * 32 + lane;
    size_t base = (size_t)b * 1048576 + h * 64;
    float s[64];
    size_t sb = (size_t)bh * 65536 + (size_t)c * 4096;
#pragma unroll
    for (int i = 0; i < 64; ++i) s[i] = g_sx[sb + i * 64 + j];
    float u0 = u[h * 64 + lane], u1 = u[h * 64 + lane + 32];
    int t0 = c * CL;
    for (int t = 0; t < CL; ++t) {
        size_t off = base + (size_t)(t0 + t) * 1024;
        float k0 = g_kk[off + lane], k1 = g_kk[off + lane + 32];
        float w0 = g_wd[off + lane], w1 = g_wd[off + lane + 32];
        float r0 = g_rr[off + lane], r1 = g_rr[off + lane + 32];
        float vj = g_vv[off + j];
        float ct = fmaf(r0 * u0, k0, r1 * u1 * k1);
#pragma unroll
        for (int o = 16; o; o >>= 1) ct += __shfl_xor_sync(0xffffffffu, ct, o);
        float y = 0.f;
#pragma unroll
        for (int i = 0; i < 32; ++i) {
            float ri = __shfl_sync(0xffffffffu, r0, i);
            float ki = __shfl_sync(0xffffffffu, k0, i);
            float wi = __shfl_sync(0xffffffffu, w0, i);
            y = fmaf(ri, s[i], y);
            s[i] = fmaf(wi, s[i], ki * vj);
        }
#pragma unroll
        for (int i = 0; i < 32; ++i) {
            float ri = __shfl_sync(0xffffffffu, r1, i);
            float ki = __shfl_sync(0xffffffffu, k1, i);
            float wi = __shfl_sync(0xffffffffu, w1, i);
            y = fmaf(ri, s[32 + i], y);
            s[32 + i] = fmaf(wi, s[32 + i], ki * vj);
        }
        y = fmaf(vj, ct, y);
        g_og[off + j] = y * 0.125f;
    }
}

__global__ void __launch_bounds__(256)
gn_kernel(const float* __restrict__ lnw, const float* __restrict__ lnb) {
    int warp = blockIdx.x * 8 + (threadIdx.x >> 5);
    int lane = threadIdx.x & 31;
    int row = warp >> 4, h = warp & 15;
    size_t off = (size_t)row * 1024 + h * 64;
    float y0 = g_og[off + lane], y1 = g_og[off + lane + 32];
    float sm = y0 + y1, sq = y0 * y0 + y1 * y1;
#pragma unroll
    for (int o = 16; o; o >>= 1) {
        sm += __shfl_xor_sync(0xffffffffu, sm, o);
        sq += __shfl_xor_sync(0xffffffffu, sq, o);
    }
    float mu  = sm * (1.f / 64.f);
    float var = sq * (1.f / 64.f) - mu * mu;
    float inv = rsqrtf(var + 1e-5f);
    float o0 = (y0 - mu) * inv * lnw[h * 64 + lane]      + lnb[h * 64 + lane];
    float o1 = (y1 - mu) * inv * lnw[h * 64 + lane + 32] + lnb[h * 64 + lane + 32];
    g_og[off + lane]      = o0 * g_gg[off + lane];
    g_og[off + lane + 32] = o1 * g_gg[off + lane + 32];
}

// ---------------- launch ----------------
extern "C" void kernel_launch(void* const* d_in, const int* in_sizes, int n_in,
                              void* d_out, int out_size) {
    const float* x          = (const float*)d_in[0];
    const float* x_maa      = (const float*)d_in[1];
    const float* w_maa      = (const float*)d_in[2];
    const float* k_maa      = (const float*)d_in[3];
    const float* v_maa      = (const float*)d_in[4];
    const float* r_maa      = (const float*)d_in[5];
    const float* gm_maa     = (const float*)d_in[6];
    const float* tm_w1      = (const float*)d_in[7];
    const float* tm_w2      = (const float*)d_in[8];
    const float* td_w1      = (const float*)d_in[9];
    const float* td_w2      = (const float*)d_in[10];
    const float* time_decay = (const float*)d_in[11];
    const float* time_first = (const float*)d_in[12];
    const float* Wr         = (const float*)d_in[13];
    const float* Wk         = (const float*)d_in[14];
    const float* Wv         = (const float*)d_in[15];
    const float* Wg         = (const float*)d_in[16];
    const float* Wo         = (const float*)d_in[17];
    const float* ln_w       = (const float*)d_in[18];
    const float* ln_b       = (const float*)d_in[19];
    float* out = (float*)d_out;

    // 1) token shift + xmix
    prep_kernel<<<(MT * CC / 4 + 255) / 256, 256>>>(x, x_maa);

    // 2) P = tanh(xmix @ tm_w1)   [4096,160]  (tf32, guarded N)
    tf32_gemm<true><<<dim3(2, 32), 256>>>(1, tm_w1, nullptr, 2, 160, CC, 1);

    // 3) five mixed inputs wx/kx/vx/rx/gx (K=32 GEMM fused with apply)
    mix_kernel<<<dim3(8, 32, 5), 256>>>(x, w_maa, k_maa, v_maa, r_maa, gm_maa, tm_w2);

    // 4) batched projections r/k/v/g (fast cp.async tf32; silu fused into g)
    tf32_proj4_fast<<<dim3(8, 32, 4), 128>>>(Wr, Wk, Wv, Wg);

    // 5) decay path: t1 = tanh(wx @ td_w1) (tf32 guarded); wd = exp(-exp(td + t1 @ td_w2)) (fp32)
    tf32_gemm<true><<<dim3(1, 32), 256>>>(3, td_w1, nullptr, 12, 64, CC, 1);
    sgemm128_wd<<<dim3(8, 32), 256>>>(td_w2, time_decay);

    // 6) WKV chunked scan
    wkv_passA<<<256, 256>>>();
    wkv_combine<<<1024, 256>>>();
    wkv_passB<<<256, 256>>>(time_first);
    gn_kernel<<<8192, 256>>>(ln_w, ln_b);

    // 7) output projection (fast tf32)
    tf32_wo_fast<<<dim3(8, 32), 128>>>(Wo, out);
}